// round 1
// baseline (speedup 1.0000x reference)
#include <cuda_runtime.h>
#include <math.h>

#define N_NODES 50000
#define E_EDGES 800000
#define DIM 128
#define NHEAD 8
#define HDIM 16
#define LN_EPS 1e-5f

// Scratch (static __device__ arrays: allocation-free per harness rules)
__device__ float d_xs[N_NODES * DIM];    // scaled source features / scaled attended
__device__ float d_agg[N_NODES * DIM];   // edge-aggregated features
__device__ int   d_deg[4 * N_NODES];     // [src1 | dst1 | src2 | dst2] degrees
__device__ float d_norm[4 * N_NODES];    // rsqrt norms, same layout

// ---------------------------------------------------------------------------
// Zeroing
// ---------------------------------------------------------------------------
__global__ void zero_all_kernel() {
    int i = blockIdx.x * blockDim.x + threadIdx.x;
    if (i < N_NODES * (DIM / 4)) {
        ((float4*)d_agg)[i] = make_float4(0.f, 0.f, 0.f, 0.f);
    }
    if (i < 4 * N_NODES) d_deg[i] = 0;
}

__global__ void zero_agg_kernel() {
    int i = blockIdx.x * blockDim.x + threadIdx.x;
    if (i < N_NODES * (DIM / 4)) {
        ((float4*)d_agg)[i] = make_float4(0.f, 0.f, 0.f, 0.f);
    }
}

// ---------------------------------------------------------------------------
// Degrees (both graphs in one pass)
// ---------------------------------------------------------------------------
__global__ void degrees_kernel(const int* __restrict__ s1, const int* __restrict__ t1,
                               const int* __restrict__ s2, const int* __restrict__ t2) {
    int i = blockIdx.x * blockDim.x + threadIdx.x;
    if (i >= E_EDGES) return;
    atomicAdd(&d_deg[0 * N_NODES + s1[i]], 1);
    atomicAdd(&d_deg[1 * N_NODES + t1[i]], 1);
    atomicAdd(&d_deg[2 * N_NODES + s2[i]], 1);
    atomicAdd(&d_deg[3 * N_NODES + t2[i]], 1);
}

__global__ void norms_kernel() {
    int i = blockIdx.x * blockDim.x + threadIdx.x;
    if (i >= 4 * N_NODES) return;
    int d = d_deg[i];
    d_norm[i] = (d > 0) ? rsqrtf((float)d) : 0.f;
}

// xs = feat * norm_src1 (per-node row scale), vectorized float4
__global__ void scale_feat_kernel(const float* __restrict__ feat) {
    int i = blockIdx.x * blockDim.x + threadIdx.x;   // float4 index
    if (i >= N_NODES * (DIM / 4)) return;
    int n = i >> 5;                                   // 32 float4 per row
    float nm = d_norm[n];
    float4 v = ((const float4*)feat)[i];
    v.x *= nm; v.y *= nm; v.z *= nm; v.w *= nm;
    ((float4*)d_xs)[i] = v;
}

// ---------------------------------------------------------------------------
// Edge gather + scatter-add: one warp per edge.
// Each lane moves a float4 (32 lanes x 16B = 512B row).
// red.global.add.v4.f32: no-return L2-side vector reduction (sm_90+).
// ---------------------------------------------------------------------------
__global__ void edge_kernel(const int* __restrict__ src, const int* __restrict__ dst) {
    int w = (blockIdx.x * blockDim.x + threadIdx.x) >> 5;
    if (w >= E_EDGES) return;
    int lane = threadIdx.x & 31;
    int s = __ldg(src + w);
    int d = __ldg(dst + w);
    const float4 v = *(const float4*)(d_xs + s * DIM + lane * 4);
    float* p = d_agg + d * DIM + lane * 4;
    asm volatile("red.global.add.v4.f32 [%0], {%1,%2,%3,%4};"
                 :: "l"(p), "f"(v.x), "f"(v.y), "f"(v.z), "f"(v.w)
                 : "memory");
}

// ---------------------------------------------------------------------------
// GEMM tiles: 64 rows x 128 cols, full K=128. 256 threads = 16(tx) x 16(ty).
// Per thread: 4 rows x 8 cols microtile.
// smem: Ws[128*128] + As[64*132 padded] + red[64*8]
// ---------------------------------------------------------------------------
#define SMEM_FLOATS (16384 + 64 * 132 + 512)
#define SMEM_BYTES  (SMEM_FLOATS * 4)

// common mainloop writes relu(acc+bias) into As (stride 132) as C
__device__ __forceinline__ void gemm_mainloop(float* Ws, float* As,
                                              const float* __restrict__ W,
                                              const float* __restrict__ bias,
                                              int norm_off, int m0) {
    int tid = threadIdx.x;
    int tx = tid & 15, ty = tid >> 4;

    // load W (4096 float4)
#pragma unroll
    for (int j = 0; j < 16; j++) {
        int idx = j * 256 + tid;
        ((float4*)Ws)[idx] = ((const float4*)W)[idx];
    }
    // load A tile with per-row dst-norm scaling (2048 float4)
#pragma unroll
    for (int j = 0; j < 8; j++) {
        int idx = j * 256 + tid;
        int r = idx >> 5, c4 = idx & 31;
        int g = m0 + r;
        float4 v = make_float4(0.f, 0.f, 0.f, 0.f);
        if (g < N_NODES) {
            v = *(const float4*)(d_agg + g * DIM + c4 * 4);
            float nm = d_norm[norm_off + g];
            v.x *= nm; v.y *= nm; v.z *= nm; v.w *= nm;
        }
        *(float4*)(As + r * 132 + c4 * 4) = v;
    }
    __syncthreads();

    float acc[4][8];
#pragma unroll
    for (int r = 0; r < 4; r++)
#pragma unroll
        for (int j = 0; j < 8; j++) acc[r][j] = 0.f;

#pragma unroll 4
    for (int k = 0; k < 128; k++) {
        float a0 = As[(ty * 4 + 0) * 132 + k];
        float a1 = As[(ty * 4 + 1) * 132 + k];
        float a2 = As[(ty * 4 + 2) * 132 + k];
        float a3 = As[(ty * 4 + 3) * 132 + k];
        float bb[8];
#pragma unroll
        for (int j = 0; j < 8; j++) bb[j] = Ws[k * 128 + tx * 8 + j];
#pragma unroll
        for (int j = 0; j < 8; j++) {
            acc[0][j] += a0 * bb[j];
            acc[1][j] += a1 * bb[j];
            acc[2][j] += a2 * bb[j];
            acc[3][j] += a3 * bb[j];
        }
    }
    __syncthreads();   // done reading As; reuse it as C tile

    float bv[8];
#pragma unroll
    for (int j = 0; j < 8; j++) bv[j] = bias[tx * 8 + j];
#pragma unroll
    for (int r = 0; r < 4; r++)
#pragma unroll
        for (int j = 0; j < 8; j++) {
            float v = acc[r][j] + bv[j];
            As[(ty * 4 + r) * 132 + tx * 8 + j] = v > 0.f ? v : 0.f;
        }
    __syncthreads();
}

// GEMM1 + per-node head attention + src2-norm prescale -> d_xs
__global__ void __launch_bounds__(256)
gemm_att_kernel(const float* __restrict__ W, const float* __restrict__ bias) {
    extern __shared__ float sm[];
    float* Ws  = sm;
    float* As  = sm + 16384;
    float* red = As + 64 * 132;
    int tid = threadIdx.x;
    int m0 = blockIdx.x * 64;

    gemm_mainloop(Ws, As, W, bias, 1 * N_NODES, m0);

    // scores: row = tid/4, each of 4 sub-threads handles 2 heads (32 cols)
    {
        int row = tid >> 2, q = tid & 3;
#pragma unroll
        for (int hh = 0; hh < 2; hh++) {
            int head = q * 2 + hh;
            float s = 0.f;
#pragma unroll
            for (int c = 0; c < HDIM; c++) {
                float v = As[row * 132 + head * HDIM + c];
                s += v * v;
            }
            red[row * 8 + head] = s * 0.25f;   // / sqrt(HD)=4
        }
    }
    __syncthreads();
    if ((tid & 3) == 0) {
        int row = tid >> 2;
        float sc[8], mx = -1e30f;
#pragma unroll
        for (int h = 0; h < 8; h++) { sc[h] = red[row * 8 + h]; mx = fmaxf(mx, sc[h]); }
        float sum = 0.f;
#pragma unroll
        for (int h = 0; h < 8; h++) { sc[h] = expf(sc[h] - mx); sum += sc[h]; }
        float inv = 1.f / sum;
#pragma unroll
        for (int h = 0; h < 8; h++) red[row * 8 + h] = sc[h] * inv;
    }
    __syncthreads();
    {
        int row = tid >> 2, q = tid & 3;
        int g = m0 + row;
        if (g < N_NODES) {
            float nm = d_norm[2 * N_NODES + g];   // src2 norm prescale
#pragma unroll
            for (int j = 0; j < 8; j++) {
                int col = q * 32 + j * 4;
                float p = red[row * 8 + (col >> 4)] * nm;
                float4 v = *(float4*)(As + row * 132 + col);
                v.x *= p; v.y *= p; v.z *= p; v.w *= p;
                *(float4*)(d_xs + g * DIM + col) = v;
            }
        }
    }
}

// GEMM2 + LayerNorm -> out
__global__ void __launch_bounds__(256)
gemm_ln_kernel(const float* __restrict__ W, const float* __restrict__ bias,
               const float* __restrict__ gamma, const float* __restrict__ beta,
               float* __restrict__ out) {
    extern __shared__ float sm[];
    float* Ws  = sm;
    float* As  = sm + 16384;
    float* red = As + 64 * 132;
    int tid = threadIdx.x;
    int m0 = blockIdx.x * 64;

    gemm_mainloop(Ws, As, W, bias, 3 * N_NODES, m0);

    // per-row mean / meansq partials: 4 sub-threads x 32 cols
    {
        int row = tid >> 2, q = tid & 3;
        float s = 0.f, s2 = 0.f;
#pragma unroll
        for (int c = 0; c < 32; c++) {
            float v = As[row * 132 + q * 32 + c];
            s += v; s2 += v * v;
        }
        red[row * 8 + q] = s;
        red[row * 8 + 4 + q] = s2;
    }
    __syncthreads();
    if ((tid & 3) == 0) {
        int row = tid >> 2;
        float s = red[row * 8 + 0] + red[row * 8 + 1] + red[row * 8 + 2] + red[row * 8 + 3];
        float s2 = red[row * 8 + 4] + red[row * 8 + 5] + red[row * 8 + 6] + red[row * 8 + 7];
        float mu = s * (1.f / 128.f);
        float var = s2 * (1.f / 128.f) - mu * mu;
        red[row * 8 + 0] = mu;
        red[row * 8 + 1] = rsqrtf(var + LN_EPS);
    }
    __syncthreads();
    {
        int row = tid >> 2, q = tid & 3;
        int g = m0 + row;
        if (g < N_NODES) {
            float mu = red[row * 8 + 0];
            float rstd = red[row * 8 + 1];
#pragma unroll
            for (int j = 0; j < 8; j++) {
                int col = q * 32 + j * 4;
                float4 v = *(float4*)(As + row * 132 + col);
                float4 gm = ((const float4*)gamma)[col >> 2];
                float4 bt = ((const float4*)beta)[col >> 2];
                v.x = (v.x - mu) * rstd * gm.x + bt.x;
                v.y = (v.y - mu) * rstd * gm.y + bt.y;
                v.z = (v.z - mu) * rstd * gm.z + bt.z;
                v.w = (v.w - mu) * rstd * gm.w + bt.w;
                *(float4*)(out + g * DIM + col) = v;
            }
        }
    }
}

// ---------------------------------------------------------------------------
extern "C" void kernel_launch(void* const* d_in, const int* in_sizes, int n_in,
                              void* d_out, int out_size) {
    const float* feat  = (const float*)d_in[0];
    const int*   src1  = (const int*)d_in[1];
    const int*   dst1  = (const int*)d_in[2];
    const int*   src2  = (const int*)d_in[3];
    const int*   dst2  = (const int*)d_in[4];
    const float* W1    = (const float*)d_in[5];
    const float* b1    = (const float*)d_in[6];
    const float* W2    = (const float*)d_in[7];
    const float* b2    = (const float*)d_in[8];
    const float* gamma = (const float*)d_in[9];
    const float* beta  = (const float*)d_in[10];
    float* out = (float*)d_out;

    cudaFuncSetAttribute(gemm_att_kernel, cudaFuncAttributeMaxDynamicSharedMemorySize, SMEM_BYTES);
    cudaFuncSetAttribute(gemm_ln_kernel,  cudaFuncAttributeMaxDynamicSharedMemorySize, SMEM_BYTES);

    const int vec4 = N_NODES * (DIM / 4);          // 1.6M float4 in agg
    zero_all_kernel<<<(vec4 + 255) / 256, 256>>>();
    degrees_kernel<<<(E_EDGES + 255) / 256, 256>>>(src1, dst1, src2, dst2);
    norms_kernel<<<(4 * N_NODES + 255) / 256, 256>>>();
    scale_feat_kernel<<<(vec4 + 255) / 256, 256>>>(feat);

    edge_kernel<<<E_EDGES / 8, 256>>>(src1, dst1);   // warp per edge
    gemm_att_kernel<<<(N_NODES + 63) / 64, 256, SMEM_BYTES>>>(W1, b1);

    zero_agg_kernel<<<(vec4 + 255) / 256, 256>>>();
    edge_kernel<<<E_EDGES / 8, 256>>>(src2, dst2);
    gemm_ln_kernel<<<(N_NODES + 63) / 64, 256, SMEM_BYTES>>>(W2, b2, gamma, beta, out);
}

// round 3
// speedup vs baseline: 1.0662x; 1.0662x over previous
#include <cuda_runtime.h>
#include <math.h>

#define N_NODES 50000
#define E_EDGES 800000
#define DIM 128
#define NHEAD 8
#define HDIM 16
#define LN_EPS 1e-5f
#define FULLMASK 0xFFFFFFFFu

// Scratch (static __device__ arrays: allocation-free per harness rules)
__device__ float d_xs[N_NODES * DIM];    // attended*norm_src2 (pass-2 gather input)
__device__ float d_agg[N_NODES * DIM];   // edge-aggregated features
__device__ int   d_deg[4 * N_NODES];     // [src1 | dst1 | src2 | dst2] degrees
__device__ float d_norm[4 * N_NODES];    // rsqrt norms, same layout
__device__ int   d_off[2 * N_NODES];     // CSR row offsets [dst1 | dst2]
__device__ int   d_cur[2 * N_NODES];     // scatter cursors
__device__ int   d_csr[2 * E_EDGES];     // CSR column (source-node) ids [g1 | g2]

// ---------------------------------------------------------------------------
__global__ void zero_deg_kernel() {
    int i = blockIdx.x * blockDim.x + threadIdx.x;
    if (i < 4 * N_NODES) d_deg[i] = 0;
}

__global__ void degrees_kernel(const int* __restrict__ s1, const int* __restrict__ t1,
                               const int* __restrict__ s2, const int* __restrict__ t2) {
    int i = blockIdx.x * blockDim.x + threadIdx.x;
    if (i >= E_EDGES) return;
    atomicAdd(&d_deg[0 * N_NODES + s1[i]], 1);
    atomicAdd(&d_deg[1 * N_NODES + t1[i]], 1);
    atomicAdd(&d_deg[2 * N_NODES + s2[i]], 1);
    atomicAdd(&d_deg[3 * N_NODES + t2[i]], 1);
}

__global__ void norms_kernel() {
    int i = blockIdx.x * blockDim.x + threadIdx.x;
    if (i >= 4 * N_NODES) return;
    int d = d_deg[i];
    d_norm[i] = (d > 0) ? rsqrtf((float)d) : 0.f;
}

// ---------------------------------------------------------------------------
// Exclusive scan of in-degrees -> CSR offsets + cursors. gridDim.x = 2 graphs.
// ---------------------------------------------------------------------------
#define SCAN_CHUNK ((N_NODES + 1023) / 1024)
__global__ void __launch_bounds__(1024) scan_kernel() {
    __shared__ int ssum[1024];
    int g = blockIdx.x;                       // 0: dst1 (deg off N), 1: dst2 (deg off 3N)
    int degoff = (g == 0 ? 1 : 3) * N_NODES;
    int t = threadIdx.x;
    int base = t * SCAN_CHUNK;

    int local = 0;
#pragma unroll
    for (int k = 0; k < SCAN_CHUNK; k++) {
        int i = base + k;
        if (i < N_NODES) local += d_deg[degoff + i];
    }
    ssum[t] = local;
    __syncthreads();
    for (int offset = 1; offset < 1024; offset <<= 1) {
        int v = (t >= offset) ? ssum[t - offset] : 0;
        __syncthreads();
        ssum[t] += v;
        __syncthreads();
    }
    int run = (t > 0) ? ssum[t - 1] : 0;      // exclusive base for this chunk
#pragma unroll
    for (int k = 0; k < SCAN_CHUNK; k++) {
        int i = base + k;
        if (i < N_NODES) {
            d_off[g * N_NODES + i] = run;
            d_cur[g * N_NODES + i] = run;
            run += d_deg[degoff + i];
        }
    }
}

// Scatter src ids into CSR. One edge of one graph per thread
// (grid covers 2*E edges; graph = idx / E). Avoids serializing two
// dependent atomic round-trips in one thread.
__global__ void scatter_kernel(const int* __restrict__ s1, const int* __restrict__ t1,
                               const int* __restrict__ s2, const int* __restrict__ t2) {
    int i = blockIdx.x * blockDim.x + threadIdx.x;
    if (i >= 2 * E_EDGES) return;
    if (i < E_EDGES) {
        int p = atomicAdd(&d_cur[0 * N_NODES + t1[i]], 1);
        d_csr[p] = s1[i];
    } else {
        int e = i - E_EDGES;
        int p = atomicAdd(&d_cur[1 * N_NODES + t2[e]], 1);
        d_csr[E_EDGES + p] = s2[e];
    }
}

// ---------------------------------------------------------------------------
// Warp-per-node CSR gather. Lane owns one float4 (32 x 16B = 512B row).
// SCALE=true: pass 1, read `xp` (feat) and scale by src1 norm.
// SCALE=false: pass 2, read d_xs (pre-scaled), no per-src scaling.
// ---------------------------------------------------------------------------
template <bool SCALE>
__global__ void __launch_bounds__(256) gather_kernel(const float* __restrict__ xp, int g) {
    int n = (blockIdx.x * blockDim.x + threadIdx.x) >> 5;
    if (n >= N_NODES) return;
    const float* x = SCALE ? xp : (const float*)d_xs;
    int lane = threadIdx.x & 31;
    int beg = d_off[g * N_NODES + n];
    int cnt = d_deg[(g == 0 ? 1 : 3) * N_NODES + n];
    const int* csr = d_csr + g * E_EDGES;

    float4 acc0 = make_float4(0.f, 0.f, 0.f, 0.f);
    float4 acc1 = make_float4(0.f, 0.f, 0.f, 0.f);

    for (int j0 = 0; j0 < cnt; j0 += 32) {
        int m = min(32, cnt - j0);
        int s_l = (lane < m) ? csr[beg + j0 + lane] : 0;
        float nm_l = 1.f;
        if (SCALE && lane < m) nm_l = d_norm[s_l];   // src1 norms at offset 0

        int jj = 0;
        for (; jj + 1 < m; jj += 2) {
            int   sA = __shfl_sync(FULLMASK, s_l, jj);
            int   sB = __shfl_sync(FULLMASK, s_l, jj + 1);
            float nA = SCALE ? __shfl_sync(FULLMASK, nm_l, jj)     : 1.f;
            float nB = SCALE ? __shfl_sync(FULLMASK, nm_l, jj + 1) : 1.f;
            float4 vA = *(const float4*)(x + sA * DIM + lane * 4);
            float4 vB = *(const float4*)(x + sB * DIM + lane * 4);
            acc0.x += vA.x * nA; acc0.y += vA.y * nA; acc0.z += vA.z * nA; acc0.w += vA.w * nA;
            acc1.x += vB.x * nB; acc1.y += vB.y * nB; acc1.z += vB.z * nB; acc1.w += vB.w * nB;
        }
        if (jj < m) {
            int   sA = __shfl_sync(FULLMASK, s_l, jj);
            float nA = SCALE ? __shfl_sync(FULLMASK, nm_l, jj) : 1.f;
            float4 vA = *(const float4*)(x + sA * DIM + lane * 4);
            acc0.x += vA.x * nA; acc0.y += vA.y * nA; acc0.z += vA.z * nA; acc0.w += vA.w * nA;
        }
    }
    acc0.x += acc1.x; acc0.y += acc1.y; acc0.z += acc1.z; acc0.w += acc1.w;
    *(float4*)(d_agg + n * DIM + lane * 4) = acc0;
}

// ---------------------------------------------------------------------------
// GEMM tiles: 64 rows x 128 cols, full K=128. 256 threads = 16(tx) x 16(ty).
// ---------------------------------------------------------------------------
#define SMEM_FLOATS (16384 + 64 * 132 + 512)
#define SMEM_BYTES  (SMEM_FLOATS * 4)

__device__ __forceinline__ void gemm_mainloop(float* Ws, float* As,
                                              const float* __restrict__ W,
                                              const float* __restrict__ bias,
                                              int norm_off, int m0) {
    int tid = threadIdx.x;
    int tx = tid & 15, ty = tid >> 4;

#pragma unroll
    for (int j = 0; j < 16; j++) {
        int idx = j * 256 + tid;
        ((float4*)Ws)[idx] = ((const float4*)W)[idx];
    }
#pragma unroll
    for (int j = 0; j < 8; j++) {
        int idx = j * 256 + tid;
        int r = idx >> 5, c4 = idx & 31;
        int g = m0 + r;
        float4 v = make_float4(0.f, 0.f, 0.f, 0.f);
        if (g < N_NODES) {
            v = *(const float4*)(d_agg + g * DIM + c4 * 4);
            float nm = d_norm[norm_off + g];
            v.x *= nm; v.y *= nm; v.z *= nm; v.w *= nm;
        }
        *(float4*)(As + r * 132 + c4 * 4) = v;
    }
    __syncthreads();

    float acc[4][8];
#pragma unroll
    for (int r = 0; r < 4; r++)
#pragma unroll
        for (int j = 0; j < 8; j++) acc[r][j] = 0.f;

#pragma unroll 4
    for (int k = 0; k < 128; k++) {
        float a0 = As[(ty * 4 + 0) * 132 + k];
        float a1 = As[(ty * 4 + 1) * 132 + k];
        float a2 = As[(ty * 4 + 2) * 132 + k];
        float a3 = As[(ty * 4 + 3) * 132 + k];
        float bb[8];
#pragma unroll
        for (int j = 0; j < 8; j++) bb[j] = Ws[k * 128 + tx * 8 + j];
#pragma unroll
        for (int j = 0; j < 8; j++) {
            acc[0][j] += a0 * bb[j];
            acc[1][j] += a1 * bb[j];
            acc[2][j] += a2 * bb[j];
            acc[3][j] += a3 * bb[j];
        }
    }
    __syncthreads();

    float bv[8];
#pragma unroll
    for (int j = 0; j < 8; j++) bv[j] = bias[tx * 8 + j];
#pragma unroll
    for (int r = 0; r < 4; r++)
#pragma unroll
        for (int j = 0; j < 8; j++) {
            float v = acc[r][j] + bv[j];
            As[(ty * 4 + r) * 132 + tx * 8 + j] = v > 0.f ? v : 0.f;
        }
    __syncthreads();
}

// GEMM1 + per-node head attention + src2-norm prescale -> d_xs
__global__ void __launch_bounds__(256)
gemm_att_kernel(const float* __restrict__ W, const float* __restrict__ bias) {
    extern __shared__ float sm[];
    float* Ws  = sm;
    float* As  = sm + 16384;
    float* red = As + 64 * 132;
    int tid = threadIdx.x;
    int m0 = blockIdx.x * 64;

    gemm_mainloop(Ws, As, W, bias, 1 * N_NODES, m0);

    {
        int row = tid >> 2, q = tid & 3;
#pragma unroll
        for (int hh = 0; hh < 2; hh++) {
            int head = q * 2 + hh;
            float s = 0.f;
#pragma unroll
            for (int c = 0; c < HDIM; c++) {
                float v = As[row * 132 + head * HDIM + c];
                s += v * v;
            }
            red[row * 8 + head] = s * 0.25f;   // / sqrt(HD)=4
        }
    }
    __syncthreads();
    if ((tid & 3) == 0) {
        int row = tid >> 2;
        float sc[8], mx = -1e30f;
#pragma unroll
        for (int h = 0; h < 8; h++) { sc[h] = red[row * 8 + h]; mx = fmaxf(mx, sc[h]); }
        float sum = 0.f;
#pragma unroll
        for (int h = 0; h < 8; h++) { sc[h] = expf(sc[h] - mx); sum += sc[h]; }
        float inv = 1.f / sum;
#pragma unroll
        for (int h = 0; h < 8; h++) red[row * 8 + h] = sc[h] * inv;
    }
    __syncthreads();
    {
        int row = tid >> 2, q = tid & 3;
        int g = m0 + row;
        if (g < N_NODES) {
            float nm = d_norm[2 * N_NODES + g];   // src2 norm prescale
#pragma unroll
            for (int j = 0; j < 8; j++) {
                int col = q * 32 + j * 4;
                float p = red[row * 8 + (col >> 4)] * nm;
                float4 v = *(float4*)(As + row * 132 + col);
                v.x *= p; v.y *= p; v.z *= p; v.w *= p;
                *(float4*)(d_xs + g * DIM + col) = v;
            }
        }
    }
}

// GEMM2 + LayerNorm -> out
__global__ void __launch_bounds__(256)
gemm_ln_kernel(const float* __restrict__ W, const float* __restrict__ bias,
               const float* __restrict__ gamma, const float* __restrict__ beta,
               float* __restrict__ out) {
    extern __shared__ float sm[];
    float* Ws  = sm;
    float* As  = sm + 16384;
    float* red = As + 64 * 132;
    int tid = threadIdx.x;
    int m0 = blockIdx.x * 64;

    gemm_mainloop(Ws, As, W, bias, 3 * N_NODES, m0);

    {
        int row = tid >> 2, q = tid & 3;
        float s = 0.f, s2 = 0.f;
#pragma unroll
        for (int c = 0; c < 32; c++) {
            float v = As[row * 132 + q * 32 + c];
            s += v; s2 += v * v;
        }
        red[row * 8 + q] = s;
        red[row * 8 + 4 + q] = s2;
    }
    __syncthreads();
    if ((tid & 3) == 0) {
        int row = tid >> 2;
        float s = red[row * 8 + 0] + red[row * 8 + 1] + red[row * 8 + 2] + red[row * 8 + 3];
        float s2 = red[row * 8 + 4] + red[row * 8 + 5] + red[row * 8 + 6] + red[row * 8 + 7];
        float mu = s * (1.f / 128.f);
        float var = s2 * (1.f / 128.f) - mu * mu;
        red[row * 8 + 0] = mu;
        red[row * 8 + 1] = rsqrtf(var + LN_EPS);
    }
    __syncthreads();
    {
        int row = tid >> 2, q = tid & 3;
        int g = m0 + row;
        if (g < N_NODES) {
            float mu = red[row * 8 + 0];
            float rstd = red[row * 8 + 1];
#pragma unroll
            for (int j = 0; j < 8; j++) {
                int col = q * 32 + j * 4;
                float4 v = *(float4*)(As + row * 132 + col);
                float4 gm = ((const float4*)gamma)[col >> 2];
                float4 bt = ((const float4*)beta)[col >> 2];
                v.x = (v.x - mu) * rstd * gm.x + bt.x;
                v.y = (v.y - mu) * rstd * gm.y + bt.y;
                v.z = (v.z - mu) * rstd * gm.z + bt.z;
                v.w = (v.w - mu) * rstd * gm.w + bt.w;
                *(float4*)(out + g * DIM + col) = v;
            }
        }
    }
}

// ---------------------------------------------------------------------------
extern "C" void kernel_launch(void* const* d_in, const int* in_sizes, int n_in,
                              void* d_out, int out_size) {
    const float* feat  = (const float*)d_in[0];
    const int*   src1  = (const int*)d_in[1];
    const int*   dst1  = (const int*)d_in[2];
    const int*   src2  = (const int*)d_in[3];
    const int*   dst2  = (const int*)d_in[4];
    const float* W1    = (const float*)d_in[5];
    const float* b1    = (const float*)d_in[6];
    const float* W2    = (const float*)d_in[7];
    const float* b2    = (const float*)d_in[8];
    const float* gamma = (const float*)d_in[9];
    const float* beta  = (const float*)d_in[10];
    float* out = (float*)d_out;

    cudaFuncSetAttribute(gemm_att_kernel, cudaFuncAttributeMaxDynamicSharedMemorySize, SMEM_BYTES);
    cudaFuncSetAttribute(gemm_ln_kernel,  cudaFuncAttributeMaxDynamicSharedMemorySize, SMEM_BYTES);

    zero_deg_kernel<<<(4 * N_NODES + 255) / 256, 256>>>();
    degrees_kernel<<<(E_EDGES + 255) / 256, 256>>>(src1, dst1, src2, dst2);
    norms_kernel<<<(4 * N_NODES + 255) / 256, 256>>>();
    scan_kernel<<<2, 1024>>>();
    scatter_kernel<<<(2 * E_EDGES + 255) / 256, 256>>>(src1, dst1, src2, dst2);

    const int gather_blocks = (N_NODES * 32 + 255) / 256;   // warp per node
    gather_kernel<true ><<<gather_blocks, 256>>>(feat, 0);
    gemm_att_kernel<<<(N_NODES + 63) / 64, 256, SMEM_BYTES>>>(W1, b1);
    gather_kernel<false><<<gather_blocks, 256>>>(nullptr, 1);   // reads d_xs internally
    gemm_ln_kernel<<<(N_NODES + 63) / 64, 256, SMEM_BYTES>>>(W2, b2, gamma, beta, out);
}

// round 4
// speedup vs baseline: 1.2613x; 1.1830x over previous
#include <cuda_runtime.h>
#include <math.h>

#define N_NODES 50000
#define E_EDGES 800000
#define DIM 128
#define NHEAD 8
#define HDIM 16
#define LN_EPS 1e-5f
#define FULLMASK 0xFFFFFFFFu
#define NB_PER_G ((N_NODES + 255) / 256)   // 196 blocks of 256 nodes per graph

// Scratch (static __device__ arrays: allocation-free per harness rules)
__device__ float d_xs[N_NODES * DIM];    // attended*norm_src2 (pass-2 gather input)
__device__ float d_agg[N_NODES * DIM];   // edge-aggregated features
__device__ int   d_deg[4 * N_NODES];     // [src1 | dst1 | src2 | dst2] degrees
__device__ float d_norm[4 * N_NODES];    // rsqrt norms, same layout
__device__ int   d_off[2 * N_NODES];     // CSR row offsets [dst1 | dst2]
__device__ int   d_cur[2 * N_NODES];     // scatter cursors
__device__ int   d_csr[2 * E_EDGES];     // CSR column (source-node) ids [g1 | g2]
__device__ int   d_bsum[2 * NB_PER_G];   // per-block degree sums
__device__ int   d_boff[2 * NB_PER_G];   // exclusive prefix of block sums

// ---------------------------------------------------------------------------
__global__ void zero_deg_kernel() {
    int i = blockIdx.x * blockDim.x + threadIdx.x;
    if (i < 4 * N_NODES) d_deg[i] = 0;
}

__global__ void degrees_kernel(const int* __restrict__ s1, const int* __restrict__ t1,
                               const int* __restrict__ s2, const int* __restrict__ t2) {
    int i = blockIdx.x * blockDim.x + threadIdx.x;
    if (i >= E_EDGES) return;
    atomicAdd(&d_deg[0 * N_NODES + s1[i]], 1);
    atomicAdd(&d_deg[1 * N_NODES + t1[i]], 1);
    atomicAdd(&d_deg[2 * N_NODES + s2[i]], 1);
    atomicAdd(&d_deg[3 * N_NODES + t2[i]], 1);
}

__global__ void norms_kernel() {
    int i = blockIdx.x * blockDim.x + threadIdx.x;
    if (i >= 4 * N_NODES) return;
    int d = d_deg[i];
    d_norm[i] = (d > 0) ? rsqrtf((float)d) : 0.f;
}

// ---------------------------------------------------------------------------
// Fully-parallel 3-phase exclusive scan of dst in-degrees -> d_off / d_cur.
// ---------------------------------------------------------------------------
// Phase A: per-block (256-node) degree sums. grid = 2 * NB_PER_G.
__global__ void __launch_bounds__(256) block_reduce_kernel() {
    int g = blockIdx.x / NB_PER_G;
    int b = blockIdx.x % NB_PER_G;
    int degoff = (g == 0 ? 1 : 3) * N_NODES;
    int n = b * 256 + threadIdx.x;
    int v = (n < N_NODES) ? d_deg[degoff + n] : 0;

    // warp reduce
#pragma unroll
    for (int o = 16; o > 0; o >>= 1) v += __shfl_down_sync(FULLMASK, v, o);
    __shared__ int ws[8];
    if ((threadIdx.x & 31) == 0) ws[threadIdx.x >> 5] = v;
    __syncthreads();
    if (threadIdx.x < 8) {
        int s = ws[threadIdx.x];
#pragma unroll
        for (int o = 4; o > 0; o >>= 1) s += __shfl_down_sync(0xFFu, s, o);
        if (threadIdx.x == 0) d_bsum[blockIdx.x] = s;
    }
}

// Phase B: one block scans the block sums of both graphs (exclusive, per graph).
__global__ void __launch_bounds__(256) bsum_scan_kernel() {
    __shared__ int ws[8];
    int t = threadIdx.x;
    int lane = t & 31, w = t >> 5;
#pragma unroll
    for (int g = 0; g < 2; g++) {
        int v = (t < NB_PER_G) ? d_bsum[g * NB_PER_G + t] : 0;
        // inclusive warp scan
        int x = v;
#pragma unroll
        for (int o = 1; o < 32; o <<= 1) {
            int y = __shfl_up_sync(FULLMASK, x, o);
            if (lane >= o) x += y;
        }
        if (lane == 31) ws[w] = x;
        __syncthreads();
        if (t < 8) {
            int s = ws[t];
#pragma unroll
            for (int o = 1; o < 8; o <<= 1) {
                int y = __shfl_up_sync(0xFFu, s, o);
                if (t >= o) s += y;
            }
            ws[t] = s;
        }
        __syncthreads();
        int base = (w > 0) ? ws[w - 1] : 0;
        if (t < NB_PER_G) d_boff[g * NB_PER_G + t] = base + x - v;   // exclusive
        __syncthreads();
    }
}

// Phase C: block-local exclusive scan + block offset -> d_off, d_cur.
__global__ void __launch_bounds__(256) offsets_kernel() {
    __shared__ int ws[8];
    int g = blockIdx.x / NB_PER_G;
    int b = blockIdx.x % NB_PER_G;
    int degoff = (g == 0 ? 1 : 3) * N_NODES;
    int t = threadIdx.x;
    int lane = t & 31, w = t >> 5;
    int n = b * 256 + t;
    int v = (n < N_NODES) ? d_deg[degoff + n] : 0;

    int x = v;
#pragma unroll
    for (int o = 1; o < 32; o <<= 1) {
        int y = __shfl_up_sync(FULLMASK, x, o);
        if (lane >= o) x += y;
    }
    if (lane == 31) ws[w] = x;
    __syncthreads();
    if (t < 8) {
        int s = ws[t];
#pragma unroll
        for (int o = 1; o < 8; o <<= 1) {
            int y = __shfl_up_sync(0xFFu, s, o);
            if (t >= o) s += y;
        }
        ws[t] = s;
    }
    __syncthreads();
    int base = d_boff[blockIdx.x] + ((w > 0) ? ws[w - 1] : 0);
    if (n < N_NODES) {
        int off = base + x - v;   // exclusive
        d_off[g * N_NODES + n] = off;
        d_cur[g * N_NODES + n] = off;
    }
}

// Scatter src ids into CSR. One edge of one graph per thread.
__global__ void scatter_kernel(const int* __restrict__ s1, const int* __restrict__ t1,
                               const int* __restrict__ s2, const int* __restrict__ t2) {
    int i = blockIdx.x * blockDim.x + threadIdx.x;
    if (i >= 2 * E_EDGES) return;
    if (i < E_EDGES) {
        int p = atomicAdd(&d_cur[0 * N_NODES + t1[i]], 1);
        d_csr[p] = s1[i];
    } else {
        int e = i - E_EDGES;
        int p = atomicAdd(&d_cur[1 * N_NODES + t2[e]], 1);
        d_csr[E_EDGES + p] = s2[e];
    }
}

// ---------------------------------------------------------------------------
// Warp-per-node CSR gather, 4 sources in flight per lane (MLP=4).
// SCALE=true: pass 1, read `xp` (feat) and scale by src1 norm.
// SCALE=false: pass 2, read d_xs (pre-scaled), no per-src scaling.
// ---------------------------------------------------------------------------
template <bool SCALE>
__global__ void __launch_bounds__(256) gather_kernel(const float* __restrict__ xp, int g) {
    int n = (blockIdx.x * blockDim.x + threadIdx.x) >> 5;
    if (n >= N_NODES) return;
    const float* x = SCALE ? xp : (const float*)d_xs;
    int lane = threadIdx.x & 31;
    int beg = d_off[g * N_NODES + n];
    int cnt = d_deg[(g == 0 ? 1 : 3) * N_NODES + n];
    const int* csr = d_csr + g * E_EDGES;

    float4 acc0 = make_float4(0.f, 0.f, 0.f, 0.f);
    float4 acc1 = make_float4(0.f, 0.f, 0.f, 0.f);
    float4 acc2 = make_float4(0.f, 0.f, 0.f, 0.f);
    float4 acc3 = make_float4(0.f, 0.f, 0.f, 0.f);

    for (int j0 = 0; j0 < cnt; j0 += 32) {
        int m = min(32, cnt - j0);
        int s_l = (lane < m) ? csr[beg + j0 + lane] : 0;
        float nm_l = 1.f;
        if (SCALE && lane < m) nm_l = d_norm[s_l];   // src1 norms at offset 0

        int jj = 0;
        for (; jj + 3 < m; jj += 4) {
            int   sA = __shfl_sync(FULLMASK, s_l, jj);
            int   sB = __shfl_sync(FULLMASK, s_l, jj + 1);
            int   sC = __shfl_sync(FULLMASK, s_l, jj + 2);
            int   sD = __shfl_sync(FULLMASK, s_l, jj + 3);
            float nA = SCALE ? __shfl_sync(FULLMASK, nm_l, jj)     : 1.f;
            float nB = SCALE ? __shfl_sync(FULLMASK, nm_l, jj + 1) : 1.f;
            float nC = SCALE ? __shfl_sync(FULLMASK, nm_l, jj + 2) : 1.f;
            float nD = SCALE ? __shfl_sync(FULLMASK, nm_l, jj + 3) : 1.f;
            float4 vA = *(const float4*)(x + sA * DIM + lane * 4);
            float4 vB = *(const float4*)(x + sB * DIM + lane * 4);
            float4 vC = *(const float4*)(x + sC * DIM + lane * 4);
            float4 vD = *(const float4*)(x + sD * DIM + lane * 4);
            acc0.x += vA.x * nA; acc0.y += vA.y * nA; acc0.z += vA.z * nA; acc0.w += vA.w * nA;
            acc1.x += vB.x * nB; acc1.y += vB.y * nB; acc1.z += vB.z * nB; acc1.w += vB.w * nB;
            acc2.x += vC.x * nC; acc2.y += vC.y * nC; acc2.z += vC.z * nC; acc2.w += vC.w * nC;
            acc3.x += vD.x * nD; acc3.y += vD.y * nD; acc3.z += vD.z * nD; acc3.w += vD.w * nD;
        }
        for (; jj < m; jj++) {
            int   sA = __shfl_sync(FULLMASK, s_l, jj);
            float nA = SCALE ? __shfl_sync(FULLMASK, nm_l, jj) : 1.f;
            float4 vA = *(const float4*)(x + sA * DIM + lane * 4);
            acc0.x += vA.x * nA; acc0.y += vA.y * nA; acc0.z += vA.z * nA; acc0.w += vA.w * nA;
        }
    }
    acc0.x += acc1.x + acc2.x + acc3.x;
    acc0.y += acc1.y + acc2.y + acc3.y;
    acc0.z += acc1.z + acc2.z + acc3.z;
    acc0.w += acc1.w + acc2.w + acc3.w;
    *(float4*)(d_agg + n * DIM + lane * 4) = acc0;
}

// ---------------------------------------------------------------------------
// GEMM tiles: 64 rows x 128 cols, full K=128. 256 threads = 16(tx) x 16(ty).
// ---------------------------------------------------------------------------
#define SMEM_FLOATS (16384 + 64 * 132 + 512)
#define SMEM_BYTES  (SMEM_FLOATS * 4)

__device__ __forceinline__ void gemm_mainloop(float* Ws, float* As,
                                              const float* __restrict__ W,
                                              const float* __restrict__ bias,
                                              int norm_off, int m0) {
    int tid = threadIdx.x;
    int tx = tid & 15, ty = tid >> 4;

#pragma unroll
    for (int j = 0; j < 16; j++) {
        int idx = j * 256 + tid;
        ((float4*)Ws)[idx] = ((const float4*)W)[idx];
    }
#pragma unroll
    for (int j = 0; j < 8; j++) {
        int idx = j * 256 + tid;
        int r = idx >> 5, c4 = idx & 31;
        int g = m0 + r;
        float4 v = make_float4(0.f, 0.f, 0.f, 0.f);
        if (g < N_NODES) {
            v = *(const float4*)(d_agg + g * DIM + c4 * 4);
            float nm = d_norm[norm_off + g];
            v.x *= nm; v.y *= nm; v.z *= nm; v.w *= nm;
        }
        *(float4*)(As + r * 132 + c4 * 4) = v;
    }
    __syncthreads();

    float acc[4][8];
#pragma unroll
    for (int r = 0; r < 4; r++)
#pragma unroll
        for (int j = 0; j < 8; j++) acc[r][j] = 0.f;

#pragma unroll 4
    for (int k = 0; k < 128; k++) {
        float a0 = As[(ty * 4 + 0) * 132 + k];
        float a1 = As[(ty * 4 + 1) * 132 + k];
        float a2 = As[(ty * 4 + 2) * 132 + k];
        float a3 = As[(ty * 4 + 3) * 132 + k];
        float bb[8];
#pragma unroll
        for (int j = 0; j < 8; j++) bb[j] = Ws[k * 128 + tx * 8 + j];
#pragma unroll
        for (int j = 0; j < 8; j++) {
            acc[0][j] += a0 * bb[j];
            acc[1][j] += a1 * bb[j];
            acc[2][j] += a2 * bb[j];
            acc[3][j] += a3 * bb[j];
        }
    }
    __syncthreads();

    float bv[8];
#pragma unroll
    for (int j = 0; j < 8; j++) bv[j] = bias[tx * 8 + j];
#pragma unroll
    for (int r = 0; r < 4; r++)
#pragma unroll
        for (int j = 0; j < 8; j++) {
            float v = acc[r][j] + bv[j];
            As[(ty * 4 + r) * 132 + tx * 8 + j] = v > 0.f ? v : 0.f;
        }
    __syncthreads();
}

// GEMM1 + per-node head attention + src2-norm prescale -> d_xs
__global__ void __launch_bounds__(256)
gemm_att_kernel(const float* __restrict__ W, const float* __restrict__ bias) {
    extern __shared__ float sm[];
    float* Ws  = sm;
    float* As  = sm + 16384;
    float* red = As + 64 * 132;
    int tid = threadIdx.x;
    int m0 = blockIdx.x * 64;

    gemm_mainloop(Ws, As, W, bias, 1 * N_NODES, m0);

    {
        int row = tid >> 2, q = tid & 3;
#pragma unroll
        for (int hh = 0; hh < 2; hh++) {
            int head = q * 2 + hh;
            float s = 0.f;
#pragma unroll
            for (int c = 0; c < HDIM; c++) {
                float v = As[row * 132 + head * HDIM + c];
                s += v * v;
            }
            red[row * 8 + head] = s * 0.25f;   // / sqrt(HD)=4
        }
    }
    __syncthreads();
    if ((tid & 3) == 0) {
        int row = tid >> 2;
        float sc[8], mx = -1e30f;
#pragma unroll
        for (int h = 0; h < 8; h++) { sc[h] = red[row * 8 + h]; mx = fmaxf(mx, sc[h]); }
        float sum = 0.f;
#pragma unroll
        for (int h = 0; h < 8; h++) { sc[h] = expf(sc[h] - mx); sum += sc[h]; }
        float inv = 1.f / sum;
#pragma unroll
        for (int h = 0; h < 8; h++) red[row * 8 + h] = sc[h] * inv;
    }
    __syncthreads();
    {
        int row = tid >> 2, q = tid & 3;
        int g = m0 + row;
        if (g < N_NODES) {
            float nm = d_norm[2 * N_NODES + g];   // src2 norm prescale
#pragma unroll
            for (int j = 0; j < 8; j++) {
                int col = q * 32 + j * 4;
                float p = red[row * 8 + (col >> 4)] * nm;
                float4 v = *(float4*)(As + row * 132 + col);
                v.x *= p; v.y *= p; v.z *= p; v.w *= p;
                *(float4*)(d_xs + g * DIM + col) = v;
            }
        }
    }
}

// GEMM2 + LayerNorm -> out
__global__ void __launch_bounds__(256)
gemm_ln_kernel(const float* __restrict__ W, const float* __restrict__ bias,
               const float* __restrict__ gamma, const float* __restrict__ beta,
               float* __restrict__ out) {
    extern __shared__ float sm[];
    float* Ws  = sm;
    float* As  = sm + 16384;
    float* red = As + 64 * 132;
    int tid = threadIdx.x;
    int m0 = blockIdx.x * 64;

    gemm_mainloop(Ws, As, W, bias, 3 * N_NODES, m0);

    {
        int row = tid >> 2, q = tid & 3;
        float s = 0.f, s2 = 0.f;
#pragma unroll
        for (int c = 0; c < 32; c++) {
            float v = As[row * 132 + q * 32 + c];
            s += v; s2 += v * v;
        }
        red[row * 8 + q] = s;
        red[row * 8 + 4 + q] = s2;
    }
    __syncthreads();
    if ((tid & 3) == 0) {
        int row = tid >> 2;
        float s = red[row * 8 + 0] + red[row * 8 + 1] + red[row * 8 + 2] + red[row * 8 + 3];
        float s2 = red[row * 8 + 4] + red[row * 8 + 5] + red[row * 8 + 6] + red[row * 8 + 7];
        float mu = s * (1.f / 128.f);
        float var = s2 * (1.f / 128.f) - mu * mu;
        red[row * 8 + 0] = mu;
        red[row * 8 + 1] = rsqrtf(var + LN_EPS);
    }
    __syncthreads();
    {
        int row = tid >> 2, q = tid & 3;
        int g = m0 + row;
        if (g < N_NODES) {
            float mu = red[row * 8 + 0];
            float rstd = red[row * 8 + 1];
#pragma unroll
            for (int j = 0; j < 8; j++) {
                int col = q * 32 + j * 4;
                float4 v = *(float4*)(As + row * 132 + col);
                float4 gm = ((const float4*)gamma)[col >> 2];
                float4 bt = ((const float4*)beta)[col >> 2];
                v.x = (v.x - mu) * rstd * gm.x + bt.x;
                v.y = (v.y - mu) * rstd * gm.y + bt.y;
                v.z = (v.z - mu) * rstd * gm.z + bt.z;
                v.w = (v.w - mu) * rstd * gm.w + bt.w;
                *(float4*)(out + g * DIM + col) = v;
            }
        }
    }
}

// ---------------------------------------------------------------------------
extern "C" void kernel_launch(void* const* d_in, const int* in_sizes, int n_in,
                              void* d_out, int out_size) {
    const float* feat  = (const float*)d_in[0];
    const int*   src1  = (const int*)d_in[1];
    const int*   dst1  = (const int*)d_in[2];
    const int*   src2  = (const int*)d_in[3];
    const int*   dst2  = (const int*)d_in[4];
    const float* W1    = (const float*)d_in[5];
    const float* b1    = (const float*)d_in[6];
    const float* W2    = (const float*)d_in[7];
    const float* b2    = (const float*)d_in[8];
    const float* gamma = (const float*)d_in[9];
    const float* beta  = (const float*)d_in[10];
    float* out = (float*)d_out;

    cudaFuncSetAttribute(gemm_att_kernel, cudaFuncAttributeMaxDynamicSharedMemorySize, SMEM_BYTES);
    cudaFuncSetAttribute(gemm_ln_kernel,  cudaFuncAttributeMaxDynamicSharedMemorySize, SMEM_BYTES);

    zero_deg_kernel<<<(4 * N_NODES + 255) / 256, 256>>>();
    degrees_kernel<<<(E_EDGES + 255) / 256, 256>>>(src1, dst1, src2, dst2);
    norms_kernel<<<(4 * N_NODES + 255) / 256, 256>>>();
    block_reduce_kernel<<<2 * NB_PER_G, 256>>>();
    bsum_scan_kernel<<<1, 256>>>();
    offsets_kernel<<<2 * NB_PER_G, 256>>>();
    scatter_kernel<<<(2 * E_EDGES + 255) / 256, 256>>>(src1, dst1, src2, dst2);

    const int gather_blocks = (N_NODES * 32 + 255) / 256;   // warp per node
    gather_kernel<true ><<<gather_blocks, 256>>>(feat, 0);
    gemm_att_kernel<<<(N_NODES + 63) / 64, 256, SMEM_BYTES>>>(W1, b1);
    gather_kernel<false><<<gather_blocks, 256>>>(nullptr, 1);   // reads d_xs internally
    gemm_ln_kernel<<<(N_NODES + 63) / 64, 256, SMEM_BYTES>>>(W2, b2, gamma, beta, out);
}

// round 5
// speedup vs baseline: 1.3590x; 1.0775x over previous
#include <cuda_runtime.h>
#include <cuda_fp16.h>
#include <math.h>

#define N_NODES 50000
#define E_EDGES 800000
#define DIM 128
#define NHEAD 8
#define HDIM 16
#define LN_EPS 1e-5f
#define FULLMASK 0xFFFFFFFFu
#define NB_PER_G ((N_NODES + 255) / 256)   // 196 blocks of 256 nodes per graph

// Scratch (static __device__ arrays: allocation-free per harness rules)
__device__ __half2 d_xh[N_NODES * 64];   // fp16 gather input (pass1: feat*norm_src1, pass2: attended*norm_src2)
__device__ float d_agg[N_NODES * DIM];   // edge-aggregated features (fp32)
__device__ int   d_deg[4 * N_NODES];     // [src1 | dst1 | src2 | dst2] degrees
__device__ float d_norm[4 * N_NODES];    // rsqrt norms, same layout
__device__ int   d_off[2 * N_NODES];     // CSR row offsets [dst1 | dst2]
__device__ int   d_cur[2 * N_NODES];     // scatter cursors
__device__ int   d_csr[2 * E_EDGES];     // CSR column (source-node) ids [g1 | g2]
__device__ int   d_bsum[2 * NB_PER_G];   // per-block dst-degree sums

// ---------------------------------------------------------------------------
__global__ void zero_deg_kernel() {
    int i = blockIdx.x * blockDim.x + threadIdx.x;
    if (i < 4 * N_NODES) d_deg[i] = 0;
}

__global__ void degrees_kernel(const int* __restrict__ s1, const int* __restrict__ t1,
                               const int* __restrict__ s2, const int* __restrict__ t2) {
    int i = blockIdx.x * blockDim.x + threadIdx.x;
    if (i >= E_EDGES) return;
    atomicAdd(&d_deg[0 * N_NODES + s1[i]], 1);
    atomicAdd(&d_deg[1 * N_NODES + t1[i]], 1);
    atomicAdd(&d_deg[2 * N_NODES + s2[i]], 1);
    atomicAdd(&d_deg[3 * N_NODES + t2[i]], 1);
}

// ---------------------------------------------------------------------------
// Fused: norms for all 4 segments + per-block dst-degree sums (segments 1,3).
// grid = 4 * NB_PER_G; segment = blockIdx.x / NB_PER_G.
// ---------------------------------------------------------------------------
__global__ void __launch_bounds__(256) norm_bsum_kernel() {
    int seg = blockIdx.x / NB_PER_G;          // 0:src1 1:dst1 2:src2 3:dst2
    int b   = blockIdx.x % NB_PER_G;
    int n   = b * 256 + threadIdx.x;
    int d = 0;
    if (n < N_NODES) {
        d = d_deg[seg * N_NODES + n];
        d_norm[seg * N_NODES + n] = (d > 0) ? rsqrtf((float)d) : 0.f;
    }
    if (seg == 1 || seg == 3) {
        int v = d;
#pragma unroll
        for (int o = 16; o > 0; o >>= 1) v += __shfl_down_sync(FULLMASK, v, o);
        __shared__ int ws[8];
        if ((threadIdx.x & 31) == 0) ws[threadIdx.x >> 5] = v;
        __syncthreads();
        if (threadIdx.x < 8) {
            int s = ws[threadIdx.x];
#pragma unroll
            for (int o = 4; o > 0; o >>= 1) s += __shfl_down_sync(0xFFu, s, o);
            if (threadIdx.x == 0) d_bsum[(seg >> 1) * NB_PER_G + b] = s;
        }
    }
}

// ---------------------------------------------------------------------------
// Offsets: inline prefix over d_bsum (196 entries) + block-local exclusive scan.
// grid = 2 * NB_PER_G.
// ---------------------------------------------------------------------------
__global__ void __launch_bounds__(256) offsets_kernel() {
    __shared__ int ws[8];
    __shared__ int sbase;
    int g = blockIdx.x / NB_PER_G;
    int b = blockIdx.x % NB_PER_G;
    int degoff = (g == 0 ? 1 : 3) * N_NODES;
    int t = threadIdx.x;
    int lane = t & 31, w = t >> 5;

    // block prefix: sum of d_bsum[g][0..b-1]
    {
        int v = (t < b) ? d_bsum[g * NB_PER_G + t] : 0;
#pragma unroll
        for (int o = 16; o > 0; o >>= 1) v += __shfl_down_sync(FULLMASK, v, o);
        if (lane == 0) ws[w] = v;
        __syncthreads();
        if (t < 8) {
            int s = ws[t];
#pragma unroll
            for (int o = 4; o > 0; o >>= 1) s += __shfl_down_sync(0xFFu, s, o);
            if (t == 0) sbase = s;
        }
        __syncthreads();
    }
    int blockbase = sbase;
    __syncthreads();

    int n = b * 256 + t;
    int v = (n < N_NODES) ? d_deg[degoff + n] : 0;
    int x = v;
#pragma unroll
    for (int o = 1; o < 32; o <<= 1) {
        int y = __shfl_up_sync(FULLMASK, x, o);
        if (lane >= o) x += y;
    }
    if (lane == 31) ws[w] = x;
    __syncthreads();
    if (t < 8) {
        int s = ws[t];
#pragma unroll
        for (int o = 1; o < 8; o <<= 1) {
            int y = __shfl_up_sync(0xFFu, s, o);
            if (t >= o) s += y;
        }
        ws[t] = s;
    }
    __syncthreads();
    int base = blockbase + ((w > 0) ? ws[w - 1] : 0);
    if (n < N_NODES) {
        int off = base + x - v;   // exclusive
        d_off[g * N_NODES + n] = off;
        d_cur[g * N_NODES + n] = off;
    }
}

// Scatter src ids into CSR. One edge of one graph per thread.
__global__ void scatter_kernel(const int* __restrict__ s1, const int* __restrict__ t1,
                               const int* __restrict__ s2, const int* __restrict__ t2) {
    int i = blockIdx.x * blockDim.x + threadIdx.x;
    if (i >= 2 * E_EDGES) return;
    if (i < E_EDGES) {
        int p = atomicAdd(&d_cur[0 * N_NODES + t1[i]], 1);
        d_csr[p] = s1[i];
    } else {
        int e = i - E_EDGES;
        int p = atomicAdd(&d_cur[1 * N_NODES + t2[e]], 1);
        d_csr[E_EDGES + p] = s2[e];
    }
}

// Convert feat * norm_src1 -> fp16 (d_xh). i indexes float4s.
__global__ void convert_kernel(const float* __restrict__ feat) {
    int i = blockIdx.x * blockDim.x + threadIdx.x;
    if (i >= N_NODES * 32) return;
    int n = i >> 5, c4 = i & 31;
    float nm = d_norm[n];                       // src1 norms at offset 0
    float4 v = ((const float4*)feat)[i];
    __half2 h0 = __floats2half2_rn(v.x * nm, v.y * nm);
    __half2 h1 = __floats2half2_rn(v.z * nm, v.w * nm);
    uint2 st;
    st.x = *(unsigned int*)&h0;
    st.y = *(unsigned int*)&h1;
    *(uint2*)(d_xh + n * 64 + c4 * 2) = st;
}

// ---------------------------------------------------------------------------
// Warp-per-node CSR gather from fp16 rows (256B/row, lane owns 8B = 4 halves).
// 4 sources in flight per lane; fp32 accumulation.
// ---------------------------------------------------------------------------
__device__ __forceinline__ void acc_half8(float4& acc, uint2 r) {
    __half2 h0 = *(__half2*)&r.x;
    __half2 h1 = *(__half2*)&r.y;
    float2 f0 = __half22float2(h0);
    float2 f1 = __half22float2(h1);
    acc.x += f0.x; acc.y += f0.y; acc.z += f1.x; acc.w += f1.y;
}

__global__ void __launch_bounds__(256) gather_kernel(int g) {
    int n = (blockIdx.x * blockDim.x + threadIdx.x) >> 5;
    if (n >= N_NODES) return;
    int lane = threadIdx.x & 31;
    int beg = d_off[g * N_NODES + n];
    int cnt = d_deg[(g == 0 ? 1 : 3) * N_NODES + n];
    const int* csr = d_csr + g * E_EDGES;

    float4 acc0 = make_float4(0.f, 0.f, 0.f, 0.f);
    float4 acc1 = make_float4(0.f, 0.f, 0.f, 0.f);
    float4 acc2 = make_float4(0.f, 0.f, 0.f, 0.f);
    float4 acc3 = make_float4(0.f, 0.f, 0.f, 0.f);

    for (int j0 = 0; j0 < cnt; j0 += 32) {
        int m = min(32, cnt - j0);
        int s_l = (lane < m) ? csr[beg + j0 + lane] : 0;
        int jj = 0;
        for (; jj + 3 < m; jj += 4) {
            int sA = __shfl_sync(FULLMASK, s_l, jj);
            int sB = __shfl_sync(FULLMASK, s_l, jj + 1);
            int sC = __shfl_sync(FULLMASK, s_l, jj + 2);
            int sD = __shfl_sync(FULLMASK, s_l, jj + 3);
            uint2 rA = *(const uint2*)(d_xh + sA * 64 + lane * 2);
            uint2 rB = *(const uint2*)(d_xh + sB * 64 + lane * 2);
            uint2 rC = *(const uint2*)(d_xh + sC * 64 + lane * 2);
            uint2 rD = *(const uint2*)(d_xh + sD * 64 + lane * 2);
            acc_half8(acc0, rA);
            acc_half8(acc1, rB);
            acc_half8(acc2, rC);
            acc_half8(acc3, rD);
        }
        for (; jj < m; jj++) {
            int sA = __shfl_sync(FULLMASK, s_l, jj);
            uint2 rA = *(const uint2*)(d_xh + sA * 64 + lane * 2);
            acc_half8(acc0, rA);
        }
    }
    acc0.x += acc1.x + acc2.x + acc3.x;
    acc0.y += acc1.y + acc2.y + acc3.y;
    acc0.z += acc1.z + acc2.z + acc3.z;
    acc0.w += acc1.w + acc2.w + acc3.w;
    *(float4*)(d_agg + n * DIM + lane * 4) = acc0;
}

// ---------------------------------------------------------------------------
// GEMM tiles: 64 rows x 128 cols, full K=128. 256 threads = 16(tx) x 16(ty).
// ---------------------------------------------------------------------------
#define SMEM_FLOATS (16384 + 64 * 132 + 512)
#define SMEM_BYTES  (SMEM_FLOATS * 4)

__device__ __forceinline__ void gemm_mainloop(float* Ws, float* As,
                                              const float* __restrict__ W,
                                              const float* __restrict__ bias,
                                              int norm_off, int m0) {
    int tid = threadIdx.x;
    int tx = tid & 15, ty = tid >> 4;

#pragma unroll
    for (int j = 0; j < 16; j++) {
        int idx = j * 256 + tid;
        ((float4*)Ws)[idx] = ((const float4*)W)[idx];
    }
#pragma unroll
    for (int j = 0; j < 8; j++) {
        int idx = j * 256 + tid;
        int r = idx >> 5, c4 = idx & 31;
        int g = m0 + r;
        float4 v = make_float4(0.f, 0.f, 0.f, 0.f);
        if (g < N_NODES) {
            v = *(const float4*)(d_agg + g * DIM + c4 * 4);
            float nm = d_norm[norm_off + g];
            v.x *= nm; v.y *= nm; v.z *= nm; v.w *= nm;
        }
        *(float4*)(As + r * 132 + c4 * 4) = v;
    }
    __syncthreads();

    float acc[4][8];
#pragma unroll
    for (int r = 0; r < 4; r++)
#pragma unroll
        for (int j = 0; j < 8; j++) acc[r][j] = 0.f;

#pragma unroll 4
    for (int k = 0; k < 128; k++) {
        float a0 = As[(ty * 4 + 0) * 132 + k];
        float a1 = As[(ty * 4 + 1) * 132 + k];
        float a2 = As[(ty * 4 + 2) * 132 + k];
        float a3 = As[(ty * 4 + 3) * 132 + k];
        float bb[8];
#pragma unroll
        for (int j = 0; j < 8; j++) bb[j] = Ws[k * 128 + tx * 8 + j];
#pragma unroll
        for (int j = 0; j < 8; j++) {
            acc[0][j] += a0 * bb[j];
            acc[1][j] += a1 * bb[j];
            acc[2][j] += a2 * bb[j];
            acc[3][j] += a3 * bb[j];
        }
    }
    __syncthreads();

    float bv[8];
#pragma unroll
    for (int j = 0; j < 8; j++) bv[j] = bias[tx * 8 + j];
#pragma unroll
    for (int r = 0; r < 4; r++)
#pragma unroll
        for (int j = 0; j < 8; j++) {
            float v = acc[r][j] + bv[j];
            As[(ty * 4 + r) * 132 + tx * 8 + j] = v > 0.f ? v : 0.f;
        }
    __syncthreads();
}

// GEMM1 + per-node head attention + src2-norm prescale -> d_xh (fp16)
__global__ void __launch_bounds__(256)
gemm_att_kernel(const float* __restrict__ W, const float* __restrict__ bias) {
    extern __shared__ float sm[];
    float* Ws  = sm;
    float* As  = sm + 16384;
    float* red = As + 64 * 132;
    int tid = threadIdx.x;
    int m0 = blockIdx.x * 64;

    gemm_mainloop(Ws, As, W, bias, 1 * N_NODES, m0);

    {
        int row = tid >> 2, q = tid & 3;
#pragma unroll
        for (int hh = 0; hh < 2; hh++) {
            int head = q * 2 + hh;
            float s = 0.f;
#pragma unroll
            for (int c = 0; c < HDIM; c++) {
                float v = As[row * 132 + head * HDIM + c];
                s += v * v;
            }
            red[row * 8 + head] = s * 0.25f;   // / sqrt(HD)=4
        }
    }
    __syncthreads();
    if ((tid & 3) == 0) {
        int row = tid >> 2;
        float sc[8], mx = -1e30f;
#pragma unroll
        for (int h = 0; h < 8; h++) { sc[h] = red[row * 8 + h]; mx = fmaxf(mx, sc[h]); }
        float sum = 0.f;
#pragma unroll
        for (int h = 0; h < 8; h++) { sc[h] = expf(sc[h] - mx); sum += sc[h]; }
        float inv = 1.f / sum;
#pragma unroll
        for (int h = 0; h < 8; h++) red[row * 8 + h] = sc[h] * inv;
    }
    __syncthreads();
    {
        int row = tid >> 2, q = tid & 3;
        int g = m0 + row;
        if (g < N_NODES) {
            float nm = d_norm[2 * N_NODES + g];   // src2 norm prescale
#pragma unroll
            for (int j = 0; j < 8; j++) {
                int col = q * 32 + j * 4;
                float p = red[row * 8 + (col >> 4)] * nm;
                float4 v = *(float4*)(As + row * 132 + col);
                __half2 h0 = __floats2half2_rn(v.x * p, v.y * p);
                __half2 h1 = __floats2half2_rn(v.z * p, v.w * p);
                uint2 st;
                st.x = *(unsigned int*)&h0;
                st.y = *(unsigned int*)&h1;
                *(uint2*)(d_xh + g * 64 + (col >> 1)) = st;
            }
        }
    }
}

// GEMM2 + LayerNorm -> out
__global__ void __launch_bounds__(256)
gemm_ln_kernel(const float* __restrict__ W, const float* __restrict__ bias,
               const float* __restrict__ gamma, const float* __restrict__ beta,
               float* __restrict__ out) {
    extern __shared__ float sm[];
    float* Ws  = sm;
    float* As  = sm + 16384;
    float* red = As + 64 * 132;
    int tid = threadIdx.x;
    int m0 = blockIdx.x * 64;

    gemm_mainloop(Ws, As, W, bias, 3 * N_NODES, m0);

    {
        int row = tid >> 2, q = tid & 3;
        float s = 0.f, s2 = 0.f;
#pragma unroll
        for (int c = 0; c < 32; c++) {
            float v = As[row * 132 + q * 32 + c];
            s += v; s2 += v * v;
        }
        red[row * 8 + q] = s;
        red[row * 8 + 4 + q] = s2;
    }
    __syncthreads();
    if ((tid & 3) == 0) {
        int row = tid >> 2;
        float s = red[row * 8 + 0] + red[row * 8 + 1] + red[row * 8 + 2] + red[row * 8 + 3];
        float s2 = red[row * 8 + 4] + red[row * 8 + 5] + red[row * 8 + 6] + red[row * 8 + 7];
        float mu = s * (1.f / 128.f);
        float var = s2 * (1.f / 128.f) - mu * mu;
        red[row * 8 + 0] = mu;
        red[row * 8 + 1] = rsqrtf(var + LN_EPS);
    }
    __syncthreads();
    {
        int row = tid >> 2, q = tid & 3;
        int g = m0 + row;
        if (g < N_NODES) {
            float mu = red[row * 8 + 0];
            float rstd = red[row * 8 + 1];
#pragma unroll
            for (int j = 0; j < 8; j++) {
                int col = q * 32 + j * 4;
                float4 v = *(float4*)(As + row * 132 + col);
                float4 gm = ((const float4*)gamma)[col >> 2];
                float4 bt = ((const float4*)beta)[col >> 2];
                v.x = (v.x - mu) * rstd * gm.x + bt.x;
                v.y = (v.y - mu) * rstd * gm.y + bt.y;
                v.z = (v.z - mu) * rstd * gm.z + bt.z;
                v.w = (v.w - mu) * rstd * gm.w + bt.w;
                *(float4*)(out + g * DIM + col) = v;
            }
        }
    }
}

// ---------------------------------------------------------------------------
extern "C" void kernel_launch(void* const* d_in, const int* in_sizes, int n_in,
                              void* d_out, int out_size) {
    const float* feat  = (const float*)d_in[0];
    const int*   src1  = (const int*)d_in[1];
    const int*   dst1  = (const int*)d_in[2];
    const int*   src2  = (const int*)d_in[3];
    const int*   dst2  = (const int*)d_in[4];
    const float* W1    = (const float*)d_in[5];
    const float* b1    = (const float*)d_in[6];
    const float* W2    = (const float*)d_in[7];
    const float* b2    = (const float*)d_in[8];
    const float* gamma = (const float*)d_in[9];
    const float* beta  = (const float*)d_in[10];
    float* out = (float*)d_out;

    cudaFuncSetAttribute(gemm_att_kernel, cudaFuncAttributeMaxDynamicSharedMemorySize, SMEM_BYTES);
    cudaFuncSetAttribute(gemm_ln_kernel,  cudaFuncAttributeMaxDynamicSharedMemorySize, SMEM_BYTES);

    zero_deg_kernel<<<(4 * N_NODES + 255) / 256, 256>>>();
    degrees_kernel<<<(E_EDGES + 255) / 256, 256>>>(src1, dst1, src2, dst2);
    norm_bsum_kernel<<<4 * NB_PER_G, 256>>>();
    offsets_kernel<<<2 * NB_PER_G, 256>>>();
    scatter_kernel<<<(2 * E_EDGES + 255) / 256, 256>>>(src1, dst1, src2, dst2);
    convert_kernel<<<(N_NODES * 32 + 255) / 256, 256>>>(feat);

    const int gather_blocks = (N_NODES * 32 + 255) / 256;   // warp per node
    gather_kernel<<<gather_blocks, 256>>>(0);
    gemm_att_kernel<<<(N_NODES + 63) / 64, 256, SMEM_BYTES>>>(W1, b1);
    gather_kernel<<<gather_blocks, 256>>>(1);
    gemm_ln_kernel<<<(N_NODES + 63) / 64, 256, SMEM_BYTES>>>(W2, b2, gamma, beta, out);
}

// round 6
// speedup vs baseline: 2.1443x; 1.5778x over previous
#include <cuda_runtime.h>
#include <cuda_fp16.h>
#include <mma.h>
#include <math.h>

using namespace nvcuda;

#define N_NODES 50000
#define E_EDGES 800000
#define DIM 128
#define NHEAD 8
#define HDIM 16
#define LN_EPS 1e-5f
#define FULLMASK 0xFFFFFFFFu
#define NB_PER_G ((N_NODES + 255) / 256)   // 196 blocks of 256 nodes per graph

// Scratch (static __device__ arrays: allocation-free per harness rules)
__device__ __half2 d_xh[N_NODES * 64];   // fp16 gather input
__device__ float d_agg[N_NODES * DIM];   // edge-aggregated features (fp32)
__device__ int   d_deg[4 * N_NODES];     // [src1 | dst1 | src2 | dst2] degrees
__device__ float d_norm[4 * N_NODES];    // rsqrt norms, same layout
__device__ int   d_off[2 * N_NODES];     // CSR row offsets [dst1 | dst2]
__device__ int   d_cur[2 * N_NODES];     // scatter cursors
__device__ int   d_csr[2 * E_EDGES];     // CSR column (source-node) ids [g1 | g2]
__device__ int   d_bsum[2 * NB_PER_G];   // per-block dst-degree sums

// ---------------------------------------------------------------------------
__global__ void zero_deg_kernel() {
    int i = blockIdx.x * blockDim.x + threadIdx.x;
    if (i < 4 * N_NODES) d_deg[i] = 0;
}

__global__ void degrees_kernel(const int* __restrict__ s1, const int* __restrict__ t1,
                               const int* __restrict__ s2, const int* __restrict__ t2) {
    int i = blockIdx.x * blockDim.x + threadIdx.x;
    if (i >= E_EDGES) return;
    atomicAdd(&d_deg[0 * N_NODES + s1[i]], 1);
    atomicAdd(&d_deg[1 * N_NODES + t1[i]], 1);
    atomicAdd(&d_deg[2 * N_NODES + s2[i]], 1);
    atomicAdd(&d_deg[3 * N_NODES + t2[i]], 1);
}

// ---------------------------------------------------------------------------
// Fused: norms for all 4 segments + per-block dst-degree sums (segments 1,3).
// ---------------------------------------------------------------------------
__global__ void __launch_bounds__(256) norm_bsum_kernel() {
    int seg = blockIdx.x / NB_PER_G;          // 0:src1 1:dst1 2:src2 3:dst2
    int b   = blockIdx.x % NB_PER_G;
    int n   = b * 256 + threadIdx.x;
    int d = 0;
    if (n < N_NODES) {
        d = d_deg[seg * N_NODES + n];
        d_norm[seg * N_NODES + n] = (d > 0) ? rsqrtf((float)d) : 0.f;
    }
    if (seg == 1 || seg == 3) {
        int v = d;
#pragma unroll
        for (int o = 16; o > 0; o >>= 1) v += __shfl_down_sync(FULLMASK, v, o);
        __shared__ int ws[8];
        if ((threadIdx.x & 31) == 0) ws[threadIdx.x >> 5] = v;
        __syncthreads();
        if (threadIdx.x < 8) {
            int s = ws[threadIdx.x];
#pragma unroll
            for (int o = 4; o > 0; o >>= 1) s += __shfl_down_sync(0xFFu, s, o);
            if (threadIdx.x == 0) d_bsum[(seg >> 1) * NB_PER_G + b] = s;
        }
    }
}

// ---------------------------------------------------------------------------
// Offsets: inline prefix over d_bsum + block-local exclusive scan.
// ---------------------------------------------------------------------------
__global__ void __launch_bounds__(256) offsets_kernel() {
    __shared__ int ws[8];
    __shared__ int sbase;
    int g = blockIdx.x / NB_PER_G;
    int b = blockIdx.x % NB_PER_G;
    int degoff = (g == 0 ? 1 : 3) * N_NODES;
    int t = threadIdx.x;
    int lane = t & 31, w = t >> 5;

    {
        int v = (t < b) ? d_bsum[g * NB_PER_G + t] : 0;
#pragma unroll
        for (int o = 16; o > 0; o >>= 1) v += __shfl_down_sync(FULLMASK, v, o);
        if (lane == 0) ws[w] = v;
        __syncthreads();
        if (t < 8) {
            int s = ws[t];
#pragma unroll
            for (int o = 4; o > 0; o >>= 1) s += __shfl_down_sync(0xFFu, s, o);
            if (t == 0) sbase = s;
        }
        __syncthreads();
    }
    int blockbase = sbase;
    __syncthreads();

    int n = b * 256 + t;
    int v = (n < N_NODES) ? d_deg[degoff + n] : 0;
    int x = v;
#pragma unroll
    for (int o = 1; o < 32; o <<= 1) {
        int y = __shfl_up_sync(FULLMASK, x, o);
        if (lane >= o) x += y;
    }
    if (lane == 31) ws[w] = x;
    __syncthreads();
    if (t < 8) {
        int s = ws[t];
#pragma unroll
        for (int o = 1; o < 8; o <<= 1) {
            int y = __shfl_up_sync(0xFFu, s, o);
            if (t >= o) s += y;
        }
        ws[t] = s;
    }
    __syncthreads();
    int base = blockbase + ((w > 0) ? ws[w - 1] : 0);
    if (n < N_NODES) {
        int off = base + x - v;   // exclusive
        d_off[g * N_NODES + n] = off;
        d_cur[g * N_NODES + n] = off;
    }
}

// ---------------------------------------------------------------------------
// Fused scatter + convert. Blocks [0, 2E/256): CSR scatter (one edge per
// thread). Blocks [2E/256, +N*32/256): convert feat*norm_src1 -> fp16.
// ---------------------------------------------------------------------------
#define SCAT_BLOCKS ((2 * E_EDGES) / 256)      // 6250
#define CONV_BLOCKS ((N_NODES * 32 + 255) / 256)
__global__ void scatter_convert_kernel(const int* __restrict__ s1, const int* __restrict__ t1,
                                       const int* __restrict__ s2, const int* __restrict__ t2,
                                       const float* __restrict__ feat) {
    int bid = blockIdx.x;
    if (bid < SCAT_BLOCKS) {
        int i = bid * 256 + threadIdx.x;
        if (i < E_EDGES) {
            int p = atomicAdd(&d_cur[0 * N_NODES + t1[i]], 1);
            d_csr[p] = s1[i];
        } else {
            int e = i - E_EDGES;
            int p = atomicAdd(&d_cur[1 * N_NODES + t2[e]], 1);
            d_csr[E_EDGES + p] = s2[e];
        }
    } else {
        int i = (bid - SCAT_BLOCKS) * 256 + threadIdx.x;
        if (i >= N_NODES * 32) return;
        int n = i >> 5, c4 = i & 31;
        float nm = d_norm[n];                       // src1 norms at offset 0
        float4 v = ((const float4*)feat)[i];
        __half2 h0 = __floats2half2_rn(v.x * nm, v.y * nm);
        __half2 h1 = __floats2half2_rn(v.z * nm, v.w * nm);
        uint2 st;
        st.x = *(unsigned int*)&h0;
        st.y = *(unsigned int*)&h1;
        *(uint2*)(d_xh + n * 64 + c4 * 2) = st;
    }
}

// ---------------------------------------------------------------------------
// Warp-per-node CSR gather from fp16 rows; fp32 accumulation, MLP=4.
// ---------------------------------------------------------------------------
__device__ __forceinline__ void acc_half8(float4& acc, uint2 r) {
    __half2 h0 = *(__half2*)&r.x;
    __half2 h1 = *(__half2*)&r.y;
    float2 f0 = __half22float2(h0);
    float2 f1 = __half22float2(h1);
    acc.x += f0.x; acc.y += f0.y; acc.z += f1.x; acc.w += f1.y;
}

__global__ void __launch_bounds__(256) gather_kernel(int g) {
    int n = (blockIdx.x * blockDim.x + threadIdx.x) >> 5;
    if (n >= N_NODES) return;
    int lane = threadIdx.x & 31;
    int beg = d_off[g * N_NODES + n];
    int cnt = d_deg[(g == 0 ? 1 : 3) * N_NODES + n];
    const int* csr = d_csr + g * E_EDGES;

    float4 acc0 = make_float4(0.f, 0.f, 0.f, 0.f);
    float4 acc1 = make_float4(0.f, 0.f, 0.f, 0.f);
    float4 acc2 = make_float4(0.f, 0.f, 0.f, 0.f);
    float4 acc3 = make_float4(0.f, 0.f, 0.f, 0.f);

    for (int j0 = 0; j0 < cnt; j0 += 32) {
        int m = min(32, cnt - j0);
        int s_l = (lane < m) ? csr[beg + j0 + lane] : 0;
        int jj = 0;
        for (; jj + 3 < m; jj += 4) {
            int sA = __shfl_sync(FULLMASK, s_l, jj);
            int sB = __shfl_sync(FULLMASK, s_l, jj + 1);
            int sC = __shfl_sync(FULLMASK, s_l, jj + 2);
            int sD = __shfl_sync(FULLMASK, s_l, jj + 3);
            uint2 rA = *(const uint2*)(d_xh + sA * 64 + lane * 2);
            uint2 rB = *(const uint2*)(d_xh + sB * 64 + lane * 2);
            uint2 rC = *(const uint2*)(d_xh + sC * 64 + lane * 2);
            uint2 rD = *(const uint2*)(d_xh + sD * 64 + lane * 2);
            acc_half8(acc0, rA);
            acc_half8(acc1, rB);
            acc_half8(acc2, rC);
            acc_half8(acc3, rD);
        }
        for (; jj < m; jj++) {
            int sA = __shfl_sync(FULLMASK, s_l, jj);
            uint2 rA = *(const uint2*)(d_xh + sA * 64 + lane * 2);
            acc_half8(acc0, rA);
        }
    }
    acc0.x += acc1.x + acc2.x + acc3.x;
    acc0.y += acc1.y + acc2.y + acc3.y;
    acc0.z += acc1.z + acc2.z + acc3.z;
    acc0.w += acc1.w + acc2.w + acc3.w;
    *(float4*)(d_agg + n * DIM + lane * 4) = acc0;
}

// ---------------------------------------------------------------------------
// Tensor-core GEMM tile: 64 rows x 128 cols, K=128. 256 threads = 8 warps.
// Warp (wm, wn) computes rows [wm*16, +16), cols [wn*64, +64) via wmma
// m16n16k16 fp16 x fp16 -> fp32.
// smem layout (bytes):
//   [0, 34816)       Ws_h: half[128][136]   (W fp16)  -- later aliased by C
//   [34816, 52224)   As_h: half[64][136]    (A fp16)
//   [52224, 54272)   red:  float[512]
//   C (fp32, 64x132) aliases [0, 33792) after mainloop.
// ---------------------------------------------------------------------------
#define WS_H_OFF 0
#define AS_H_OFF 34816
#define RED_OFF  52224
#define SMEM_BYTES 54272
#define A_LDH 136
#define C_LDF 132

__device__ __forceinline__ void wmma_mainloop(char* smem,
                                              const float* __restrict__ W,
                                              const float* __restrict__ bias,
                                              int norm_off, int m0) {
    __half* Ws = (__half*)(smem + WS_H_OFF);
    __half* As = (__half*)(smem + AS_H_OFF);
    float*  C  = (float*)smem;
    int tid = threadIdx.x;

    // W (128x128 fp32) -> fp16 smem, ld=136
#pragma unroll
    for (int j = 0; j < 16; j++) {
        int idx = j * 256 + tid;          // float4 index, 4096 total
        int row = idx >> 5, c4 = idx & 31;
        float4 v = ((const float4*)W)[idx];
        __half2 h0 = __floats2half2_rn(v.x, v.y);
        __half2 h1 = __floats2half2_rn(v.z, v.w);
        uint2 st;
        st.x = *(unsigned int*)&h0;
        st.y = *(unsigned int*)&h1;
        *(uint2*)(Ws + row * A_LDH + c4 * 4) = st;
    }
    // A tile (64x128) with per-row dst-norm scale -> fp16 smem
#pragma unroll
    for (int j = 0; j < 8; j++) {
        int idx = j * 256 + tid;          // 2048 float4
        int r = idx >> 5, c4 = idx & 31;
        int g = m0 + r;
        float4 v = make_float4(0.f, 0.f, 0.f, 0.f);
        float nm = 0.f;
        if (g < N_NODES) {
            v = *(const float4*)(d_agg + g * DIM + c4 * 4);
            nm = d_norm[norm_off + g];
        }
        __half2 h0 = __floats2half2_rn(v.x * nm, v.y * nm);
        __half2 h1 = __floats2half2_rn(v.z * nm, v.w * nm);
        uint2 st;
        st.x = *(unsigned int*)&h0;
        st.y = *(unsigned int*)&h1;
        *(uint2*)(As + r * A_LDH + c4 * 4) = st;
    }
    __syncthreads();

    int wid = tid >> 5;
    int wm = wid & 3;       // 4 row-groups of 16
    int wn = wid >> 2;      // 2 col-groups of 64

    wmma::fragment<wmma::accumulator, 16, 16, 16, float> acc[4];
#pragma unroll
    for (int n = 0; n < 4; n++) wmma::fill_fragment(acc[n], 0.f);

#pragma unroll
    for (int k = 0; k < 8; k++) {
        wmma::fragment<wmma::matrix_a, 16, 16, 16, __half, wmma::row_major> fa;
        wmma::load_matrix_sync(fa, As + (wm * 16) * A_LDH + k * 16, A_LDH);
#pragma unroll
        for (int n = 0; n < 4; n++) {
            wmma::fragment<wmma::matrix_b, 16, 16, 16, __half, wmma::row_major> fb;
            wmma::load_matrix_sync(fb, Ws + (k * 16) * A_LDH + wn * 64 + n * 16, A_LDH);
            wmma::mma_sync(acc[n], fa, fb, acc[n]);
        }
    }
    __syncthreads();   // done reading Ws/As; C aliases Ws region

#pragma unroll
    for (int n = 0; n < 4; n++)
        wmma::store_matrix_sync(C + (wm * 16) * C_LDF + wn * 64 + n * 16,
                                acc[n], C_LDF, wmma::mem_row_major);
    __syncthreads();

    // bias + ReLU in place
#pragma unroll
    for (int j = 0; j < 8; j++) {
        int idx = j * 256 + tid;
        int r = idx >> 5, c4 = idx & 31;
        float4 v = *(float4*)(C + r * C_LDF + c4 * 4);
        float4 bv = ((const float4*)bias)[c4];
        v.x = fmaxf(v.x + bv.x, 0.f);
        v.y = fmaxf(v.y + bv.y, 0.f);
        v.z = fmaxf(v.z + bv.z, 0.f);
        v.w = fmaxf(v.w + bv.w, 0.f);
        *(float4*)(C + r * C_LDF + c4 * 4) = v;
    }
    __syncthreads();
}

// GEMM1 + per-node head attention + src2-norm prescale -> d_xh (fp16)
__global__ void __launch_bounds__(256)
gemm_att_kernel(const float* __restrict__ W, const float* __restrict__ bias) {
    extern __shared__ char smc[];
    float* As  = (float*)smc;                 // C tile
    float* red = (float*)(smc + RED_OFF);
    int tid = threadIdx.x;
    int m0 = blockIdx.x * 64;

    wmma_mainloop(smc, W, bias, 1 * N_NODES, m0);

    {
        int row = tid >> 2, q = tid & 3;
#pragma unroll
        for (int hh = 0; hh < 2; hh++) {
            int head = q * 2 + hh;
            float s = 0.f;
#pragma unroll
            for (int c = 0; c < HDIM; c++) {
                float v = As[row * C_LDF + head * HDIM + c];
                s += v * v;
            }
            red[row * 8 + head] = s * 0.25f;   // / sqrt(HD)=4
        }
    }
    __syncthreads();
    if ((tid & 3) == 0) {
        int row = tid >> 2;
        float sc[8], mx = -1e30f;
#pragma unroll
        for (int h = 0; h < 8; h++) { sc[h] = red[row * 8 + h]; mx = fmaxf(mx, sc[h]); }
        float sum = 0.f;
#pragma unroll
        for (int h = 0; h < 8; h++) { sc[h] = expf(sc[h] - mx); sum += sc[h]; }
        float inv = 1.f / sum;
#pragma unroll
        for (int h = 0; h < 8; h++) red[row * 8 + h] = sc[h] * inv;
    }
    __syncthreads();
    {
        int row = tid >> 2, q = tid & 3;
        int g = m0 + row;
        if (g < N_NODES) {
            float nm = d_norm[2 * N_NODES + g];   // src2 norm prescale
#pragma unroll
            for (int j = 0; j < 8; j++) {
                int col = q * 32 + j * 4;
                float p = red[row * 8 + (col >> 4)] * nm;
                float4 v = *(float4*)(As + row * C_LDF + col);
                __half2 h0 = __floats2half2_rn(v.x * p, v.y * p);
                __half2 h1 = __floats2half2_rn(v.z * p, v.w * p);
                uint2 st;
                st.x = *(unsigned int*)&h0;
                st.y = *(unsigned int*)&h1;
                *(uint2*)(d_xh + g * 64 + (col >> 1)) = st;
            }
        }
    }
}

// GEMM2 + LayerNorm -> out
__global__ void __launch_bounds__(256)
gemm_ln_kernel(const float* __restrict__ W, const float* __restrict__ bias,
               const float* __restrict__ gamma, const float* __restrict__ beta,
               float* __restrict__ out) {
    extern __shared__ char smc[];
    float* As  = (float*)smc;                 // C tile
    float* red = (float*)(smc + RED_OFF);
    int tid = threadIdx.x;
    int m0 = blockIdx.x * 64;

    wmma_mainloop(smc, W, bias, 3 * N_NODES, m0);

    {
        int row = tid >> 2, q = tid & 3;
        float s = 0.f, s2 = 0.f;
#pragma unroll
        for (int c = 0; c < 32; c++) {
            float v = As[row * C_LDF + q * 32 + c];
            s += v; s2 += v * v;
        }
        red[row * 8 + q] = s;
        red[row * 8 + 4 + q] = s2;
    }
    __syncthreads();
    if ((tid & 3) == 0) {
        int row = tid >> 2;
        float s = red[row * 8 + 0] + red[row * 8 + 1] + red[row * 8 + 2] + red[row * 8 + 3];
        float s2 = red[row * 8 + 4] + red[row * 8 + 5] + red[row * 8 + 6] + red[row * 8 + 7];
        float mu = s * (1.f / 128.f);
        float var = s2 * (1.f / 128.f) - mu * mu;
        red[row * 8 + 0] = mu;
        red[row * 8 + 1] = rsqrtf(var + LN_EPS);
    }
    __syncthreads();
    {
        int row = tid >> 2, q = tid & 3;
        int g = m0 + row;
        if (g < N_NODES) {
            float mu = red[row * 8 + 0];
            float rstd = red[row * 8 + 1];
#pragma unroll
            for (int j = 0; j < 8; j++) {
                int col = q * 32 + j * 4;
                float4 v = *(float4*)(As + row * C_LDF + col);
                float4 gm = ((const float4*)gamma)[col >> 2];
                float4 bt = ((const float4*)beta)[col >> 2];
                v.x = (v.x - mu) * rstd * gm.x + bt.x;
                v.y = (v.y - mu) * rstd * gm.y + bt.y;
                v.z = (v.z - mu) * rstd * gm.z + bt.z;
                v.w = (v.w - mu) * rstd * gm.w + bt.w;
                *(float4*)(out + g * DIM + col) = v;
            }
        }
    }
}

// ---------------------------------------------------------------------------
extern "C" void kernel_launch(void* const* d_in, const int* in_sizes, int n_in,
                              void* d_out, int out_size) {
    const float* feat  = (const float*)d_in[0];
    const int*   src1  = (const int*)d_in[1];
    const int*   dst1  = (const int*)d_in[2];
    const int*   src2  = (const int*)d_in[3];
    const int*   dst2  = (const int*)d_in[4];
    const float* W1    = (const float*)d_in[5];
    const float* b1    = (const float*)d_in[6];
    const float* W2    = (const float*)d_in[7];
    const float* b2    = (const float*)d_in[8];
    const float* gamma = (const float*)d_in[9];
    const float* beta  = (const float*)d_in[10];
    float* out = (float*)d_out;

    cudaFuncSetAttribute(gemm_att_kernel, cudaFuncAttributeMaxDynamicSharedMemorySize, SMEM_BYTES);
    cudaFuncSetAttribute(gemm_ln_kernel,  cudaFuncAttributeMaxDynamicSharedMemorySize, SMEM_BYTES);

    zero_deg_kernel<<<(4 * N_NODES + 255) / 256, 256>>>();
    degrees_kernel<<<(E_EDGES + 255) / 256, 256>>>(src1, dst1, src2, dst2);
    norm_bsum_kernel<<<4 * NB_PER_G, 256>>>();
    offsets_kernel<<<2 * NB_PER_G, 256>>>();
    scatter_convert_kernel<<<SCAT_BLOCKS + CONV_BLOCKS, 256>>>(src1, dst1, src2, dst2, feat);

    const int gather_blocks = (N_NODES * 32 + 255) / 256;   // warp per node
    gather_kernel<<<gather_blocks, 256>>>(0);
    gemm_att_kernel<<<(N_NODES + 63) / 64, 256, SMEM_BYTES>>>(W1, b1);
    gather_kernel<<<gather_blocks, 256>>>(1);
    gemm_ln_kernel<<<(N_NODES + 63) / 64, 256, SMEM_BYTES>>>(W2, b2, gamma, beta, out);
}